// round 6
// baseline (speedup 1.0000x reference)
#include <cuda_runtime.h>
#include <cuda_fp16.h>
#include <cstdint>

#define IN_F  4096
#define OUT_F 4096
#define NFAC  3

// ---------------- scratch (device globals; allocation forbidden) -----------
__device__ __align__(1024) float  g_Q[NFAC * 64 * 64 * 64];
__device__ int    g_pinv[NFAC * IN_F];
__device__ __align__(1024) float  g_w0[(size_t)OUT_F * IN_F];        // 64 MB
__device__ __align__(1024) float  g_w1[(size_t)OUT_F * IN_F];        // 64 MB
__device__ __align__(1024) __half g_wh[(size_t)OUT_F * IN_F];        // 32 MB
__device__ __align__(1024) __half g_xh[(size_t)8 * 2048 * IN_F];     // 128 MB

// ---------------- helpers ---------------------------------------------------
__device__ __forceinline__ uint32_t smem_u32(const void* p) {
    uint32_t a;
    asm("{ .reg .u64 t; cvta.to.shared.u64 t, %1; cvt.u32.u64 %0, t; }" : "=r"(a) : "l"(p));
    return a;
}
#define CP_ASYNC16(dst, src) \
    asm volatile("cp.async.cg.shared.global [%0], [%1], 16;" :: "r"(dst), "l"(src) : "memory")
#define CP_COMMIT()  asm volatile("cp.async.commit_group;" ::: "memory")
#define CP_WAIT1()   asm volatile("cp.async.wait_group 1;" ::: "memory")

#define LDSM4(r, addr) \
    asm volatile("ldmatrix.sync.aligned.m8n8.x4.shared.b16 {%0,%1,%2,%3}, [%4];" \
        : "=r"((r)[0]), "=r"((r)[1]), "=r"((r)[2]), "=r"((r)[3]) : "r"(addr))

#define MMA16816(c, a, b0v, b1v) \
    asm volatile("mma.sync.aligned.m16n8k16.row.col.f32.f16.f16.f32 " \
        "{%0,%1,%2,%3},{%4,%5,%6,%7},{%8,%9},{%0,%1,%2,%3};" \
        : "+f"((c)[0]), "+f"((c)[1]), "+f"((c)[2]), "+f"((c)[3]) \
        : "r"((a)[0]), "r"((a)[1]), "r"((a)[2]), "r"((a)[3]), "r"(b0v), "r"(b1v))

// ------- Cayley (blocks 0..191) + inverse permutation (block 192) ----------
__global__ void cayley_pinv_kernel(const float* __restrict__ R_all,
                                   const int* __restrict__ perm)
{
    const int tid = threadIdx.x;
    if (blockIdx.x >= 192) {                     // pinv part
        for (int idx = tid; idx < NFAC * IN_F; idx += 256) {
            int f = idx >> 12, j = idx & 4095;
            g_pinv[(f << 12) + perm[idx]] = j;
        }
        return;
    }

    __shared__ float aug[64][129];
    const int m   = blockIdx.x;
    const float* R = R_all + (size_t)m * 4096;

    for (int idx = tid; idx < 4096; idx += 256) {
        int i = idx >> 6, j = idx & 63;
        float s = 0.5f * (R[i * 64 + j] - R[j * 64 + i]);
        float d = (i == j) ? 1.0f : 0.0f;
        aug[i][j]      = d - s;
        aug[i][64 + j] = d + s;
    }
    __syncthreads();

    const int r  = tid >> 2;
    const int c0 = tid & 3;
    for (int k = 0; k < 64; k++) {
        float inv = 1.0f / aug[k][k];
        __syncthreads();
        if (tid < 32) {
            #pragma unroll
            for (int i = 0; i < 4; i++) aug[k][tid + 32 * i] *= inv;
        }
        __syncthreads();
        float f = aug[r][k];
        __syncthreads();
        if (r != k) {
            #pragma unroll
            for (int i = 0; i < 32; i++) {
                int c = c0 + 4 * i;
                aug[r][c] -= f * aug[k][c];
            }
        }
        __syncthreads();
    }

    float* Qm = g_Q + (size_t)m * 4096;
    for (int idx = tid; idx < 4096; idx += 256) {
        int a = idx >> 6, b = idx & 63;
        Qm[a * 64 + b] = aug[b][64 + a];
    }
}

// ---------------- x -> fp16 ----------------
__global__ void convert_x(const float4* __restrict__ in, uint4* __restrict__ out)
{
    int i = blockIdx.x * 256 + threadIdx.x;
    float4 a = in[2 * i], b = in[2 * i + 1];
    __half2 h0 = __floats2half2_rn(a.x, a.y);
    __half2 h1 = __floats2half2_rn(a.z, a.w);
    __half2 h2 = __floats2half2_rn(b.x, b.y);
    __half2 h3 = __floats2half2_rn(b.z, b.w);
    uint4 v;
    v.x = *(uint32_t*)&h0; v.y = *(uint32_t*)&h1;
    v.z = *(uint32_t*)&h2; v.w = *(uint32_t*)&h3;
    out[i] = v;
}

// ---------------- one butterfly factor applied to W columns ----------------
__global__ __launch_bounds__(256) void rot_kernel(
    const float* __restrict__ Win, float* __restrict__ Wout,
    __half* __restrict__ Wh, int factor, const float* __restrict__ s)
{
    __shared__ float Qs[64][68];
    __shared__ float Ts[64][68];
    __shared__ int   cs[64];

    const int d   = blockIdx.x;
    const int rg  = blockIdx.y;
    const int tid = threadIdx.x;

    const float* Qm = g_Q + ((size_t)factor * 64 + d) * 4096;
    #pragma unroll
    for (int i = 0; i < 4; i++) {
        int q = tid + 256 * i;
        int row = q >> 4, c4 = (q & 15) * 4;
        *(float4*)&Qs[row][c4] = *(const float4*)&Qm[row * 64 + c4];
    }
    if (tid < 64) cs[tid] = g_pinv[factor * IN_F + d * 64 + tid];
    __syncthreads();

    const int row0 = rg * 64;
    #pragma unroll
    for (int i = 0; i < 4; i++) {
        int q = tid + 256 * i;
        int rr = q >> 4, b0 = (q & 15) * 4;
        *(float4*)&Ts[rr][b0] = *(const float4*)&Win[(size_t)(row0 + rr) * IN_F + cs[b0]];
    }
    __syncthreads();

    const int a  = tid & 63;
    const int r0 = tid >> 6;
    float acc[16];
    #pragma unroll
    for (int j = 0; j < 16; j++) acc[j] = 0.0f;

    for (int b4 = 0; b4 < 16; b4++) {
        float4 q = *(const float4*)&Qs[a][b4 * 4];
        #pragma unroll
        for (int j = 0; j < 16; j++) {
            float4 t = *(const float4*)&Ts[r0 * 16 + j][b4 * 4];
            acc[j] += q.x * t.x + q.y * t.y + q.z * t.z + q.w * t.w;
        }
    }

    const int col = cs[a];
    #pragma unroll
    for (int j = 0; j < 16; j++) {
        int rr = row0 + r0 * 16 + j;
        if (s) Wh[(size_t)rr * IN_F + col] = __float2half_rn(acc[j] * s[rr]);
        else   Wout[(size_t)rr * IN_F + col] = acc[j];
    }
}

// ---------------- fp16 mma.sync GEMM: C[16384,4096] = A * B^T + bias -------
// CTA 128x128, 4 warps (2x2), warp tile 64x64, BK=64, 3 stages, 2 CTAs/SM.
#define BKH 64
#define AST 16384
#define STG 32768
#define STAGES 3
#define SMEM_TOTAL (STAGES * STG)       // 98304

__global__ __launch_bounds__(128, 2) void gemm_hmma(
    const __half* __restrict__ A, const __half* __restrict__ B,
    const float* __restrict__ bias, float* __restrict__ C)
{
    extern __shared__ char smem[];
    const uint32_t sb = smem_u32(smem);
    const int tid = threadIdx.x;
    const int wid = tid >> 5, lid = tid & 31;
    const int wm  = wid >> 1, wn = wid & 1;
    const int m0  = blockIdx.y * 128;
    const int n0  = blockIdx.x * 128;

    float acc[4][4][2][4];
    #pragma unroll
    for (int mi = 0; mi < 4; mi++)
        #pragma unroll
        for (int g = 0; g < 4; g++)
            #pragma unroll
            for (int j = 0; j < 2; j++)
                #pragma unroll
                for (int k = 0; k < 4; k++) acc[mi][g][j][k] = 0.0f;

    auto load_stage = [&](int st, int kt) {
        const uint32_t ab = sb + st * STG;
        const uint32_t bb = ab + AST;
        const __half* Ag = A + (size_t)m0 * IN_F + kt * BKH;
        const __half* Bg = B + (size_t)n0 * IN_F + kt * BKH;
        #pragma unroll
        for (int i = 0; i < 8; i++) {
            int q = tid + 128 * i;
            int r = q >> 3, c = q & 7;
            CP_ASYNC16(ab + r * 128 + ((c ^ (r & 7)) << 4), Ag + (size_t)r * IN_F + c * 8);
        }
        #pragma unroll
        for (int i = 0; i < 8; i++) {
            int q = tid + 128 * i;
            int r = q >> 3, c = q & 7;
            CP_ASYNC16(bb + r * 128 + ((c ^ (r & 7)) << 4), Bg + (size_t)r * IN_F + c * 8);
        }
    };

    load_stage(0, 0); CP_COMMIT();
    load_stage(1, 1); CP_COMMIT();

    const int lrow = (lid & 7) + ((lid >> 3) & 1) * 8;
    const int lkhi = (lid >> 4) & 1;
    const int rowx = lrow & 7;

    uint32_t afr[2][4][4], bfr[2][4][4];     // kk double buffer

    const int NK = IN_F / BKH;    // 64
    for (int kt = 0; kt < NK; kt++) {
        CP_WAIT1();
        __syncthreads();
        // issue next stage's loads FIRST so DRAM latency overlaps the MMAs
        if (kt + 2 < NK) load_stage((kt + 2) % STAGES, kt + 2);
        CP_COMMIT();

        const uint32_t as = sb + (kt % STAGES) * STG;
        const uint32_t bs = as + AST;
        const uint32_t a_base = as + (wm * 64 + lrow) * 128;
        const uint32_t b_base = bs + (wn * 64 + lrow) * 128;

        // prefetch kk = 0 fragments
        {
            const uint32_t coff = ((lkhi ^ rowx) << 4);
            #pragma unroll
            for (int mi = 0; mi < 4; mi++) LDSM4(afr[0][mi], a_base + mi * 2048 + coff);
            #pragma unroll
            for (int g = 0; g < 4; g++)    LDSM4(bfr[0][g],  b_base + g * 2048 + coff);
        }

        #pragma unroll
        for (int kk = 0; kk < 4; kk++) {
            const int cur = kk & 1, nxt = cur ^ 1;
            if (kk < 3) {
                const uint32_t coff = (((((kk + 1) << 1) | lkhi) ^ rowx) << 4);
                #pragma unroll
                for (int mi = 0; mi < 4; mi++) LDSM4(afr[nxt][mi], a_base + mi * 2048 + coff);
                #pragma unroll
                for (int g = 0; g < 4; g++)    LDSM4(bfr[nxt][g],  b_base + g * 2048 + coff);
            }
            #pragma unroll
            for (int mi = 0; mi < 4; mi++)
                #pragma unroll
                for (int g = 0; g < 4; g++) {
                    MMA16816(acc[mi][g][0], afr[cur][mi], bfr[cur][g][0], bfr[cur][g][2]);
                    MMA16816(acc[mi][g][1], afr[cur][mi], bfr[cur][g][1], bfr[cur][g][3]);
                }
        }
    }

    // epilogue: fused bias, float2 stores
    const int mrow = lid >> 2;
    const int ncl  = (lid & 3) * 2;
    #pragma unroll
    for (int g = 0; g < 4; g++)
        #pragma unroll
        for (int j = 0; j < 2; j++) {
            int n = n0 + wn * 64 + g * 16 + j * 8 + ncl;
            float2 bv = *(const float2*)&bias[n];
            #pragma unroll
            for (int mi = 0; mi < 4; mi++) {
                int m = m0 + wm * 64 + mi * 16 + mrow;
                float* a4 = acc[mi][g][j];
                float2 v0 = { a4[0] + bv.x, a4[1] + bv.y };
                float2 v1 = { a4[2] + bv.x, a4[3] + bv.y };
                *(float2*)&C[(size_t)m * OUT_F + n]       = v0;
                *(float2*)&C[(size_t)(m + 8) * OUT_F + n] = v1;
            }
        }
}

// ---------------- launch ----------------
extern "C" void kernel_launch(void* const* d_in, const int* in_sizes, int n_in,
                              void* d_out, int out_size)
{
    const float* x      = (const float*)d_in[0];
    const float* weight = (const float*)d_in[1];
    const float* bias   = (const float*)d_in[2];
    const float* boft_R = (const float*)d_in[3];
    const float* boft_s = (const float*)d_in[4];
    const int*   perm   = (const int*)d_in[5];
    float* out = (float*)d_out;

    float *w0, *w1; __half *wh, *xh;
    cudaGetSymbolAddress((void**)&w0, g_w0);
    cudaGetSymbolAddress((void**)&w1, g_w1);
    cudaGetSymbolAddress((void**)&wh, g_wh);
    cudaGetSymbolAddress((void**)&xh, g_xh);

    cayley_pinv_kernel<<<193, 256>>>(boft_R, perm);     // launch 0
    convert_x<<<32768, 256>>>((const float4*)x, (uint4*)xh);            // 1
    rot_kernel<<<dim3(64, 64), 256>>>(weight, w0, nullptr, 0, nullptr); // 2
    rot_kernel<<<dim3(64, 64), 256>>>(w0,     w1, nullptr, 1, nullptr); // 3
    rot_kernel<<<dim3(64, 64), 256>>>(w1, nullptr, wh,     2, boft_s);  // 4

    cudaFuncSetAttribute(gemm_hmma, cudaFuncAttributeMaxDynamicSharedMemorySize, SMEM_TOTAL);
    gemm_hmma<<<dim3(OUT_F / 128, 16384 / 128), 128, SMEM_TOTAL>>>(xh, wh, bias, out);  // 5 -> profiled
}

// round 7
// speedup vs baseline: 1.0458x; 1.0458x over previous
#include <cuda_runtime.h>
#include <cuda_fp16.h>
#include <cstdint>

#define IN_F  4096
#define OUT_F 4096
#define NFAC  3

// ---------------- scratch (device globals; allocation forbidden) -----------
__device__ __align__(1024) float  g_Q[NFAC * 64 * 64 * 64];
__device__ int    g_pinv[NFAC * IN_F];
__device__ __align__(1024) float  g_w0[(size_t)OUT_F * IN_F];        // 64 MB
__device__ __align__(1024) float  g_w1[(size_t)OUT_F * IN_F];        // 64 MB
__device__ __align__(1024) __half g_wh[(size_t)OUT_F * IN_F];        // 32 MB
__device__ __align__(1024) __half g_xh[(size_t)8 * 2048 * IN_F];     // 128 MB

// ---------------- helpers ---------------------------------------------------
__device__ __forceinline__ uint32_t smem_u32(const void* p) {
    uint32_t a;
    asm("{ .reg .u64 t; cvta.to.shared.u64 t, %1; cvt.u32.u64 %0, t; }" : "=r"(a) : "l"(p));
    return a;
}
#define CP_ASYNC16(dst, src) \
    asm volatile("cp.async.cg.shared.global [%0], [%1], 16;" :: "r"(dst), "l"(src) : "memory")
#define CP_COMMIT()  asm volatile("cp.async.commit_group;" ::: "memory")
#define CP_WAIT1()   asm volatile("cp.async.wait_group 1;" ::: "memory")

#define LDSM4(r, addr) \
    asm volatile("ldmatrix.sync.aligned.m8n8.x4.shared.b16 {%0,%1,%2,%3}, [%4];" \
        : "=r"((r)[0]), "=r"((r)[1]), "=r"((r)[2]), "=r"((r)[3]) : "r"(addr))

#define MMA16816(c, a, b0v, b1v) \
    asm volatile("mma.sync.aligned.m16n8k16.row.col.f32.f16.f16.f32 " \
        "{%0,%1,%2,%3},{%4,%5,%6,%7},{%8,%9},{%0,%1,%2,%3};" \
        : "+f"((c)[0]), "+f"((c)[1]), "+f"((c)[2]), "+f"((c)[3]) \
        : "r"((a)[0]), "r"((a)[1]), "r"((a)[2]), "r"((a)[3]), "r"(b0v), "r"(b1v))

// ---- fused prep: Cayley (0..191) | pinv (192) | x->fp16 (193..) -----------
__global__ void prep_kernel(const float* __restrict__ R_all,
                            const int* __restrict__ perm,
                            const float4* __restrict__ xin,
                            uint4* __restrict__ xout)
{
    const int tid = threadIdx.x;
    const int bid = blockIdx.x;

    if (bid > 192) {                 // x conversion: one uint4 out per thread
        int i = (bid - 193) * 256 + tid;
        float4 a = xin[2 * i], b = xin[2 * i + 1];
        __half2 h0 = __floats2half2_rn(a.x, a.y);
        __half2 h1 = __floats2half2_rn(a.z, a.w);
        __half2 h2 = __floats2half2_rn(b.x, b.y);
        __half2 h3 = __floats2half2_rn(b.z, b.w);
        uint4 v;
        v.x = *(uint32_t*)&h0; v.y = *(uint32_t*)&h1;
        v.z = *(uint32_t*)&h2; v.w = *(uint32_t*)&h3;
        xout[i] = v;
        return;
    }
    if (bid == 192) {                // inverse permutation
        for (int idx = tid; idx < NFAC * IN_F; idx += 256) {
            int f = idx >> 12, j = idx & 4095;
            g_pinv[(f << 12) + perm[idx]] = j;
        }
        return;
    }

    // Cayley: Q = (I-S)(I+S)^-1 via GJ on [I-S | I+S]
    __shared__ float aug[64][129];
    const float* R = R_all + (size_t)bid * 4096;

    for (int idx = tid; idx < 4096; idx += 256) {
        int i = idx >> 6, j = idx & 63;
        float s = 0.5f * (R[i * 64 + j] - R[j * 64 + i]);
        float d = (i == j) ? 1.0f : 0.0f;
        aug[i][j]      = d - s;
        aug[i][64 + j] = d + s;
    }
    __syncthreads();

    const int r  = tid >> 2;
    const int c0 = tid & 3;
    for (int k = 0; k < 64; k++) {
        float inv = 1.0f / aug[k][k];
        __syncthreads();
        if (tid < 32) {
            #pragma unroll
            for (int i = 0; i < 4; i++) aug[k][tid + 32 * i] *= inv;
        }
        __syncthreads();
        float f = aug[r][k];
        __syncthreads();
        if (r != k) {
            #pragma unroll
            for (int i = 0; i < 32; i++) {
                int c = c0 + 4 * i;
                aug[r][c] -= f * aug[k][c];
            }
        }
        __syncthreads();
    }

    float* Qm = g_Q + (size_t)bid * 4096;
    for (int idx = tid; idx < 4096; idx += 256) {
        int a = idx >> 6, b = idx & 63;
        Qm[a * 64 + b] = aug[b][64 + a];
    }
}

// ---------------- one butterfly factor applied to W columns ----------------
__global__ __launch_bounds__(256) void rot_kernel(
    const float* __restrict__ Win, float* __restrict__ Wout,
    __half* __restrict__ Wh, int factor, const float* __restrict__ s)
{
    __shared__ float Qs[64][68];
    __shared__ float Ts[64][68];
    __shared__ int   cs[64];

    const int d   = blockIdx.x;
    const int rg  = blockIdx.y;
    const int tid = threadIdx.x;

    const float* Qm = g_Q + ((size_t)factor * 64 + d) * 4096;
    #pragma unroll
    for (int i = 0; i < 4; i++) {
        int q = tid + 256 * i;
        int row = q >> 4, c4 = (q & 15) * 4;
        *(float4*)&Qs[row][c4] = *(const float4*)&Qm[row * 64 + c4];
    }
    if (tid < 64) cs[tid] = g_pinv[factor * IN_F + d * 64 + tid];
    __syncthreads();

    const int row0 = rg * 64;
    #pragma unroll
    for (int i = 0; i < 4; i++) {
        int q = tid + 256 * i;
        int rr = q >> 4, b0 = (q & 15) * 4;
        *(float4*)&Ts[rr][b0] = *(const float4*)&Win[(size_t)(row0 + rr) * IN_F + cs[b0]];
    }
    __syncthreads();

    const int a  = tid & 63;
    const int r0 = tid >> 6;
    float acc[16];
    #pragma unroll
    for (int j = 0; j < 16; j++) acc[j] = 0.0f;

    for (int b4 = 0; b4 < 16; b4++) {
        float4 q = *(const float4*)&Qs[a][b4 * 4];
        #pragma unroll
        for (int j = 0; j < 16; j++) {
            float4 t = *(const float4*)&Ts[r0 * 16 + j][b4 * 4];
            acc[j] += q.x * t.x + q.y * t.y + q.z * t.z + q.w * t.w;
        }
    }

    const int col = cs[a];
    #pragma unroll
    for (int j = 0; j < 16; j++) {
        int rr = row0 + r0 * 16 + j;
        if (s) Wh[(size_t)rr * IN_F + col] = __float2half_rn(acc[j] * s[rr]);
        else   Wout[(size_t)rr * IN_F + col] = acc[j];
    }
}

// ---------------- fp16 mma.sync GEMM: C[16384,4096] = A * B^T + bias -------
// CTA 128x128, 4 warps (2x2), warp tile 64x64, BK=64, 3 stages, 2 CTAs/SM.
#define BKH 64
#define AST 16384
#define STG 32768
#define STAGES 3
#define SMEM_TOTAL (STAGES * STG)       // 98304

__global__ __launch_bounds__(128, 2) void gemm_hmma(
    const __half* __restrict__ A, const __half* __restrict__ B,
    const float* __restrict__ bias, float* __restrict__ C)
{
    extern __shared__ char smem[];
    const uint32_t sb = smem_u32(smem);
    const int tid = threadIdx.x;
    const int wid = tid >> 5, lid = tid & 31;
    const int wm  = wid >> 1, wn = wid & 1;
    const int m0  = blockIdx.y * 128;
    const int n0  = blockIdx.x * 128;

    float acc[4][4][2][4];
    #pragma unroll
    for (int mi = 0; mi < 4; mi++)
        #pragma unroll
        for (int g = 0; g < 4; g++)
            #pragma unroll
            for (int j = 0; j < 2; j++)
                #pragma unroll
                for (int k = 0; k < 4; k++) acc[mi][g][j][k] = 0.0f;

    auto load_stage = [&](int st, int kt) {
        const uint32_t ab = sb + st * STG;
        const uint32_t bb = ab + AST;
        const __half* Ag = A + (size_t)m0 * IN_F + kt * BKH;
        const __half* Bg = B + (size_t)n0 * IN_F + kt * BKH;
        #pragma unroll
        for (int i = 0; i < 8; i++) {
            int q = tid + 128 * i;
            int r = q >> 3, c = q & 7;
            CP_ASYNC16(ab + r * 128 + ((c ^ (r & 7)) << 4), Ag + (size_t)r * IN_F + c * 8);
        }
        #pragma unroll
        for (int i = 0; i < 8; i++) {
            int q = tid + 128 * i;
            int r = q >> 3, c = q & 7;
            CP_ASYNC16(bb + r * 128 + ((c ^ (r & 7)) << 4), Bg + (size_t)r * IN_F + c * 8);
        }
    };

    load_stage(0, 0); CP_COMMIT();
    load_stage(1, 1); CP_COMMIT();

    const int lrow = (lid & 7) + ((lid >> 3) & 1) * 8;
    const int lkhi = (lid >> 4) & 1;
    const int rowx = lrow & 7;

    const int NK = IN_F / BKH;    // 64
    for (int kt = 0; kt < NK; kt++) {
        CP_WAIT1();
        __syncthreads();
        const uint32_t as = sb + (kt % STAGES) * STG;
        const uint32_t bs = as + AST;
        const uint32_t a_base = as + (wm * 64 + lrow) * 128;
        const uint32_t b_base = bs + (wn * 64 + lrow) * 128;

        #pragma unroll
        for (int kk = 0; kk < 4; kk++) {
            const uint32_t coff = ((((kk << 1) | lkhi) ^ rowx) << 4);
            uint32_t afr[4][4];
            #pragma unroll
            for (int mi = 0; mi < 4; mi++)
                LDSM4(afr[mi], a_base + mi * 2048 + coff);
            uint32_t bfr[4][4];
            #pragma unroll
            for (int g = 0; g < 4; g++)
                LDSM4(bfr[g], b_base + g * 2048 + coff);
            #pragma unroll
            for (int mi = 0; mi < 4; mi++)
                #pragma unroll
                for (int g = 0; g < 4; g++) {
                    MMA16816(acc[mi][g][0], afr[mi], bfr[g][0], bfr[g][2]);
                    MMA16816(acc[mi][g][1], afr[mi], bfr[g][1], bfr[g][3]);
                }
        }

        if (kt + 2 < NK) load_stage((kt + 2) % STAGES, kt + 2);
        CP_COMMIT();
    }

    // epilogue: fused bias, float2 stores
    const int mrow = lid >> 2;
    const int ncl  = (lid & 3) * 2;
    #pragma unroll
    for (int g = 0; g < 4; g++)
        #pragma unroll
        for (int j = 0; j < 2; j++) {
            int n = n0 + wn * 64 + g * 16 + j * 8 + ncl;
            float2 bv = *(const float2*)&bias[n];
            #pragma unroll
            for (int mi = 0; mi < 4; mi++) {
                int m = m0 + wm * 64 + mi * 16 + mrow;
                float* a4 = acc[mi][g][j];
                float2 v0 = { a4[0] + bv.x, a4[1] + bv.y };
                float2 v1 = { a4[2] + bv.x, a4[3] + bv.y };
                *(float2*)&C[(size_t)m * OUT_F + n]       = v0;
                *(float2*)&C[(size_t)(m + 8) * OUT_F + n] = v1;
            }
        }
}

// ---------------- launch ----------------
extern "C" void kernel_launch(void* const* d_in, const int* in_sizes, int n_in,
                              void* d_out, int out_size)
{
    const float* x      = (const float*)d_in[0];
    const float* weight = (const float*)d_in[1];
    const float* bias   = (const float*)d_in[2];
    const float* boft_R = (const float*)d_in[3];
    const float* boft_s = (const float*)d_in[4];
    const int*   perm   = (const int*)d_in[5];
    float* out = (float*)d_out;

    float *w0, *w1; __half *wh, *xh;
    cudaGetSymbolAddress((void**)&w0, g_w0);
    cudaGetSymbolAddress((void**)&w1, g_w1);
    cudaGetSymbolAddress((void**)&wh, g_wh);
    cudaGetSymbolAddress((void**)&xh, g_xh);

    prep_kernel<<<193 + 32768, 256>>>(boft_R, perm, (const float4*)x, (uint4*)xh);  // 0
    rot_kernel<<<dim3(64, 64), 256>>>(weight, w0, nullptr, 0, nullptr);             // 1
    rot_kernel<<<dim3(64, 64), 256>>>(w0,     w1, nullptr, 1, nullptr);             // 2
    rot_kernel<<<dim3(64, 64), 256>>>(w1, nullptr, wh,     2, boft_s);              // 3

    cudaFuncSetAttribute(gemm_hmma, cudaFuncAttributeMaxDynamicSharedMemorySize, SMEM_TOTAL);
    gemm_hmma<<<dim3(OUT_F / 128, 16384 / 128), 128, SMEM_TOTAL>>>(xh, wh, bias, out);  // 4 -> profiled
}